// round 1
// baseline (speedup 1.0000x reference)
#include <cuda_runtime.h>
#include <cuda_bf16.h>
#include <math.h>

// ---------------------------------------------------------------------------
// CapacityNN: PINN-style tanh MLP (2 -> 256 -> 256 -> 256 -> 256 -> 1) with
// forward-mode 1st and 2nd derivatives w.r.t. t_norm, + Verhulst logistic terms.
//
// Activation layout: rows = point*3 + stream  (stream 0=value, 1=d/dtn, 2=d2/dtn2)
// so each hidden-layer GEMM block tile (32 points x 3 streams = 96 rows) can do
// the tanh chain-rule coupling entirely in its epilogue.
// ---------------------------------------------------------------------------

#define NPTS 65536              // 512 * 128
#define HDIM 256

// ping-pong activation scratch: [NPTS*3][256] floats each (201 MB each)
__device__ float g_actA[(size_t)NPTS * 3 * HDIM];
__device__ float g_actB[(size_t)NPTS * 3 * HDIM];

// ---------------------------------------------------------------------------
// Layer 0: x = [s_norm, t_norm], tangent of t_norm is 1.
// z = W0 x + b0 ; z' = W0[:,1] ; z'' = 0
// h = tanh(z); h' = (1-h^2) z' ; h'' = -2 h z' h'
// ---------------------------------------------------------------------------
__global__ void layer0_kernel(const float* __restrict__ in,
                              const float* __restrict__ W0,
                              const float* __restrict__ b0,
                              const float* __restrict__ in_mean,
                              const float* __restrict__ in_std,
                              float* __restrict__ H, int n)
{
    int gid = blockIdx.x * blockDim.x + threadIdx.x;
    if (gid >= n * HDIM) return;
    int p = gid >> 8;
    int o = gid & 255;

    float s  = in[p * 2 + 0];
    float tt = in[p * 2 + 1];
    float sn = (s  - in_mean[0]) / (in_std[0] + 1e-8f);
    float tn = (tt - in_mean[1]) / (in_std[1] + 1e-8f);

    float w0 = W0[o * 2 + 0];
    float w1 = W0[o * 2 + 1];
    float z  = fmaf(w0, sn, fmaf(w1, tn, b0[o]));

    float a   = tanhf(z);
    float g   = 1.0f - a * a;
    float hp  = g * w1;             // z' = w1, z'' = 0
    float hpp = -2.0f * a * w1 * hp;

    size_t rb = (size_t)p * 3 * HDIM;
    H[rb + o]            = a;
    H[rb + HDIM + o]     = hp;
    H[rb + 2 * HDIM + o] = hpp;
}

// ---------------------------------------------------------------------------
// Hidden layer: GEMM [96 rows x 256 cols] per block, K=256, fused tanh coupling.
// Block tile: 32 points (96 rows: 3p+s), full 256 output dims.
// 256 threads: (tx,ty) in 16x16, microtile 6 rows x 16 cols each.
// Rows 6*ty..6*ty+5 = points {2ty, 2ty+1} with all 3 streams -> local epilogue.
// ---------------------------------------------------------------------------
__global__ void __launch_bounds__(256, 1)
layer_kernel(const float* __restrict__ A,
             const float* __restrict__ W,
             const float* __restrict__ b,
             float* __restrict__ H)
{
    __shared__ float sA[16][97];    // [k][row]   (pad 97: conflict-free)
    __shared__ float sB[16][257];   // [k][odim]  (pad 257: conflict-free)

    const int t  = threadIdx.x;
    const int tx = t & 15;
    const int ty = t >> 4;
    const size_t rowBase = (size_t)blockIdx.x * 96;

    float acc[6][16];
    #pragma unroll
    for (int i = 0; i < 6; i++)
        #pragma unroll
        for (int j = 0; j < 16; j++)
            acc[i][j] = 0.0f;

    for (int kt = 0; kt < HDIM; kt += 16) {
        __syncthreads();
        // stage A tile: 96 rows x 16 k, float4 per thread-iter
        #pragma unroll
        for (int idx = t; idx < 384; idx += 256) {
            int r  = idx >> 2;
            int kq = (idx & 3) << 2;
            float4 v = *(const float4*)(A + (rowBase + r) * HDIM + kt + kq);
            sA[kq + 0][r] = v.x; sA[kq + 1][r] = v.y;
            sA[kq + 2][r] = v.z; sA[kq + 3][r] = v.w;
        }
        // stage W tile: 256 odims x 16 k (W is [out][in] row-major)
        #pragma unroll
        for (int idx = t; idx < 1024; idx += 256) {
            int o  = idx >> 2;
            int kq = (idx & 3) << 2;
            float4 v = *(const float4*)(W + o * HDIM + kt + kq);
            sB[kq + 0][o] = v.x; sB[kq + 1][o] = v.y;
            sB[kq + 2][o] = v.z; sB[kq + 3][o] = v.w;
        }
        __syncthreads();

        #pragma unroll
        for (int kk = 0; kk < 16; kk++) {
            float af[6], bf[16];
            #pragma unroll
            for (int i = 0; i < 6; i++) af[i] = sA[kk][6 * ty + i];
            #pragma unroll
            for (int j = 0; j < 16; j++) bf[j] = sB[kk][tx + 16 * j];
            #pragma unroll
            for (int i = 0; i < 6; i++)
                #pragma unroll
                for (int j = 0; j < 16; j++)
                    acc[i][j] = fmaf(af[i], bf[j], acc[i][j]);
        }
    }

    // epilogue: tanh chain rule coupling across the 3 streams, write H
    #pragma unroll
    for (int j = 0; j < 16; j++) {
        int o = tx + 16 * j;
        float bv = __ldg(b + o);
        #pragma unroll
        for (int pp = 0; pp < 2; pp++) {
            float z   = acc[3 * pp + 0][j] + bv;
            float zp  = acc[3 * pp + 1][j];
            float zpp = acc[3 * pp + 2][j];
            float a   = tanhf(z);
            float g   = 1.0f - a * a;
            float hp  = g * zp;
            float hpp = fmaf(g, zpp, -2.0f * a * zp * hp);
            size_t rb = rowBase + 6 * ty + 3 * pp;
            H[(rb + 0) * HDIM + o] = a;
            H[(rb + 1) * HDIM + o] = hp;
            H[(rb + 2) * HDIM + o] = hpp;
        }
    }
}

// ---------------------------------------------------------------------------
// Final head: one warp per point. u = W4 . h + b4 (per stream), then
// U = u0*ts + tm; U_t = u1*ts; U_tt = u2*ts
// G = r(U-C)(1-(U-C)/(K-C)); F = U_t - G
// G_t = r*U_t*(1 - 2(U-C)/(K-C)); F_t = U_tt - G_t
// ---------------------------------------------------------------------------
__global__ void final_kernel(const float* __restrict__ A,
                             const float* __restrict__ W4,
                             const float* __restrict__ b4,
                             const float* __restrict__ lgr,
                             const float* __restrict__ lcc,
                             const float* __restrict__ lil,
                             const float* __restrict__ tgt_mean,
                             const float* __restrict__ tgt_std,
                             float* __restrict__ out, int n)
{
    int warp = (blockIdx.x * blockDim.x + threadIdx.x) >> 5;
    int ln   = threadIdx.x & 31;
    if (warp >= n) return;

    float sums[3];
    #pragma unroll
    for (int s = 0; s < 3; s++) {
        const float* base = A + ((size_t)warp * 3 + s) * HDIM;
        float acc = 0.0f;
        #pragma unroll
        for (int k = ln; k < HDIM; k += 32)
            acc = fmaf(base[k], __ldg(W4 + k), acc);
        #pragma unroll
        for (int off = 16; off > 0; off >>= 1)
            acc += __shfl_xor_sync(0xffffffffu, acc, off);
        sums[s] = acc;
    }

    if (ln == 0) {
        float ts = tgt_std[0];
        float tm = tgt_mean[0];
        float r_ = expf(-lgr[0]);
        float Kc = 0.2f + 0.8f / (1.0f + expf(-lcc[0]));
        float Cc = 0.1f / (1.0f + expf(-lil[0]));

        float U   = (sums[0] + b4[0]) * ts + tm;
        float Ut  = sums[1] * ts;
        float Utt = sums[2] * ts;

        float d  = (U - Cc) / (Kc - Cc);
        float G  = r_ * (U - Cc) * (1.0f - d);
        float F  = Ut - G;
        float Gt = r_ * Ut * (1.0f - 2.0f * d);
        float Ft = Utt - Gt;

        out[warp]         = U;
        out[n + warp]     = F;
        out[2 * n + warp] = Ft;
    }
}

// ---------------------------------------------------------------------------
extern "C" void kernel_launch(void* const* d_in, const int* in_sizes, int n_in,
                              void* d_out, int out_size)
{
    const float* inputs  = (const float*)d_in[0];
    const float* W0      = (const float*)d_in[1];
    const float* b0      = (const float*)d_in[2];
    const float* W1      = (const float*)d_in[3];
    const float* b1      = (const float*)d_in[4];
    const float* W2      = (const float*)d_in[5];
    const float* b2      = (const float*)d_in[6];
    const float* W3      = (const float*)d_in[7];
    const float* b3      = (const float*)d_in[8];
    const float* W4      = (const float*)d_in[9];
    const float* b4      = (const float*)d_in[10];
    const float* lgr     = (const float*)d_in[11];
    const float* lcc     = (const float*)d_in[12];
    const float* lil     = (const float*)d_in[13];
    const float* in_mean = (const float*)d_in[14];
    const float* in_std  = (const float*)d_in[15];
    const float* tgt_mean= (const float*)d_in[16];
    const float* tgt_std = (const float*)d_in[17];

    int n = in_sizes[0] / 2;   // number of points (B*S)
    if (n > NPTS) n = NPTS;

    float *actA, *actB;
    cudaGetSymbolAddress((void**)&actA, g_actA);
    cudaGetSymbolAddress((void**)&actB, g_actB);

    layer0_kernel<<<(n * HDIM + 255) / 256, 256>>>(inputs, W0, b0, in_mean, in_std, actA, n);
    layer_kernel<<<n / 32, 256>>>(actA, W1, b1, actB);
    layer_kernel<<<n / 32, 256>>>(actB, W2, b2, actA);
    layer_kernel<<<n / 32, 256>>>(actA, W3, b3, actB);
    final_kernel<<<(n + 7) / 8, 256>>>(actB, W4, b4, lgr, lcc, lil,
                                       tgt_mean, tgt_std, (float*)d_out, n);
}

// round 3
// speedup vs baseline: 2.6795x; 2.6795x over previous
#include <cuda_runtime.h>
#include <cuda_bf16.h>
#include <math.h>
#include <stdint.h>

// ---------------------------------------------------------------------------
// CapacityNN on tcgen05: tanh MLP (2->256->256->256->256->1) with forward-mode
// 1st/2nd derivatives w.r.t t_norm. Hidden-layer GEMMs run on tensor cores in
// split-precision bf16 (hi/lo, 3 products = ~fp32 accuracy), fp32 TMEM accum,
// tanh chain-rule coupling fused in the TMEM epilogue.
//
// tcgen05 code is guarded for the arch-specific sm_103a pass only; the
// compute_103 generic-PTX fallback pass gets a stub (never executed: the
// sm_103a cubin is an exact match at load time).
// ---------------------------------------------------------------------------

#if defined(__CUDA_ARCH_FEAT_SM103_ALL) || \
    (defined(__CUDA_ARCH_SPECIFIC__) && (__CUDA_ARCH_SPECIFIC__ == 1030))
#define HAS_TCGEN05 1
#else
#define HAS_TCGEN05 0
#endif

#define NPTS 65536
#define HDIM 256
#define PLANE ((size_t)NPTS * HDIM)

__device__ uint32_t g_actA[3 * PLANE];
__device__ uint32_t g_actB[3 * PLANE];
__device__ uint32_t g_Wpk[3 * HDIM * HDIM];

// ---------------- PTX helpers ------------------------------------------------
__device__ __forceinline__ uint32_t smem_u32(const void* p) {
    uint32_t a;
    asm("{ .reg .u64 t; cvta.to.shared.u64 t, %1; cvt.u32.u64 %0, t; }"
        : "=r"(a) : "l"(p));
    return a;
}
__device__ __forceinline__ uint32_t elect_one() {
    uint32_t pred;
    asm volatile("{\n\t.reg .pred p;\n\telect.sync _|p, 0xFFFFFFFF;\n\t"
                 "selp.b32 %0, 1, 0, p;\n\t}" : "=r"(pred));
    return pred;
}
#define SWZ128(o) ((o) ^ (((o) >> 3) & 0x70))

static constexpr uint64_t DESC_BASE_SW128 =
    (2ULL << 61) | (1ULL << 46) | (64ULL << 32) | (1ULL << 16);
__device__ __forceinline__ uint64_t mk_desc(uint32_t addr) {
    return DESC_BASE_SW128 | ((uint64_t)(addr >> 4) & 0x3FFF);
}

// idesc: dtype=F32, atype=BF16, btype=BF16, N=128, M=128 (cta_group::1)
#define MMA_IDESC 0x08200490u

__device__ __forceinline__ void mma_f16_ss(uint32_t d, uint64_t a, uint64_t b,
                                           uint32_t en) {
#if HAS_TCGEN05
    asm volatile(
        "{\n\t.reg .pred p;\n\tsetp.ne.u32 p, %4, 0;\n\t"
        "tcgen05.mma.cta_group::1.kind::f16 [%0], %1, %2, %3, {%5,%5,%5,%5}, p;\n\t}"
        :: "r"(d), "l"(a), "l"(b), "r"(MMA_IDESC), "r"(en), "r"(0u)
        : "memory");
#endif
}
__device__ __forceinline__ void tc_alloc(uint32_t sm, uint32_t n) {
#if HAS_TCGEN05
    asm volatile("tcgen05.alloc.cta_group::1.sync.aligned.shared::cta.b32 [%0], %1;"
                 :: "r"(sm), "r"(n) : "memory");
#endif
}
__device__ __forceinline__ void tc_relinq() {
#if HAS_TCGEN05
    asm volatile("tcgen05.relinquish_alloc_permit.cta_group::1.sync.aligned;");
#endif
}
__device__ __forceinline__ void tc_dealloc(uint32_t t, uint32_t n) {
#if HAS_TCGEN05
    asm volatile("tcgen05.dealloc.cta_group::1.sync.aligned.b32 %0, %1;"
                 :: "r"(t), "r"(n));
#endif
}
__device__ __forceinline__ void tc_commit(uint32_t mb) {
#if HAS_TCGEN05
    asm volatile("tcgen05.commit.cta_group::1.mbarrier::arrive::one.shared::cluster.b64 [%0];"
                 :: "r"(mb) : "memory");
#endif
}
__device__ __forceinline__ void tc_fence_after() {
#if HAS_TCGEN05
    asm volatile("tcgen05.fence::after_thread_sync;" ::: "memory");
#endif
}
__device__ __forceinline__ void tc_wait_ld() {
#if HAS_TCGEN05
    asm volatile("tcgen05.wait::ld.sync.aligned;" ::: "memory");
#endif
}
__device__ __forceinline__ void mbar_init(uint32_t mb, uint32_t n) {
    asm volatile("mbarrier.init.shared.b64 [%0], %1;" :: "r"(mb), "r"(n) : "memory");
}
__device__ __forceinline__ void fence_async() {
    asm volatile("fence.proxy.async.shared::cta;" ::: "memory");
}
__device__ __forceinline__ void mbar_wait(uint32_t mb, uint32_t parity) {
    uint32_t done;
    asm volatile(
        "{\n\t.reg .pred p;\n\t"
        "mbarrier.try_wait.parity.acquire.cta.shared::cta.b64 p, [%1], %2;\n\t"
        "selp.b32 %0, 1, 0, p;\n\t}"
        : "=r"(done) : "r"(mb), "r"(parity) : "memory");
    if (!done) {
        asm volatile(
            "{\n\t.reg .pred P1;\n\t"
            "WL_%=:\n\t"
            "mbarrier.try_wait.parity.acquire.cta.shared::cta.b64 P1, [%0], %1, 0x989680;\n\t"
            "@P1 bra.uni WD_%=;\n\t"
            "bra.uni WL_%=;\n\t"
            "WD_%=:\n\t}"
            :: "r"(mb), "r"(parity) : "memory");
    }
}
__device__ __forceinline__ void ldtm_x8(uint32_t* r, uint32_t addr) {
#if HAS_TCGEN05
    asm volatile("tcgen05.ld.sync.aligned.32x32b.x8.b32 "
                 "{%0,%1,%2,%3,%4,%5,%6,%7}, [%8];"
                 : "=r"(r[0]), "=r"(r[1]), "=r"(r[2]), "=r"(r[3]),
                   "=r"(r[4]), "=r"(r[5]), "=r"(r[6]), "=r"(r[7])
                 : "r"(addr));
#else
    for (int i = 0; i < 8; i++) r[i] = 0;
#endif
}

// split fp32 -> packed (bf16 hi | bf16 lo << 16)
__device__ __forceinline__ uint32_t pack_hl(float x) {
    __nv_bfloat16 h = __float2bfloat16(x);
    float hf = __bfloat162float(h);
    __nv_bfloat16 l = __float2bfloat16(x - hf);
    return (uint32_t)__bfloat16_as_ushort(h) |
           ((uint32_t)__bfloat16_as_ushort(l) << 16);
}

// ---------------- weight packing ---------------------------------------------
__global__ void pack_weights_kernel(const float* __restrict__ W1,
                                    const float* __restrict__ W2,
                                    const float* __restrict__ W3,
                                    uint32_t* __restrict__ out) {
    int idx = blockIdx.x * blockDim.x + threadIdx.x;
    if (idx >= 3 * HDIM * HDIM) return;
    const float* W = (idx < HDIM * HDIM) ? W1
                     : (idx < 2 * HDIM * HDIM) ? W2 : W3;
    out[idx] = pack_hl(W[idx % (HDIM * HDIM)]);
}

// ---------------- layer 0 -----------------------------------------------------
__global__ void layer0_kernel(const float* __restrict__ in,
                              const float* __restrict__ W0,
                              const float* __restrict__ b0,
                              const float* __restrict__ in_mean,
                              const float* __restrict__ in_std,
                              uint32_t* __restrict__ H, int n)
{
    int gid = blockIdx.x * blockDim.x + threadIdx.x;
    if (gid >= n * HDIM) return;
    int p = gid >> 8;
    int o = gid & 255;

    float s  = in[p * 2 + 0];
    float tt = in[p * 2 + 1];
    float sn = (s  - in_mean[0]) / (in_std[0] + 1e-8f);
    float tn = (tt - in_mean[1]) / (in_std[1] + 1e-8f);

    float w0 = W0[o * 2 + 0];
    float w1 = W0[o * 2 + 1];
    float z  = fmaf(w0, sn, fmaf(w1, tn, b0[o]));

    float a   = tanhf(z);
    float g   = 1.0f - a * a;
    float hp  = g * w1;
    float hpp = -2.0f * a * w1 * hp;

    size_t off = (size_t)p * HDIM + o;
    H[off]             = pack_hl(a);
    H[PLANE + off]     = pack_hl(hp);
    H[2 * PLANE + off] = pack_hl(hpp);
}

// ---------------- tcgen05 hidden layer ---------------------------------------
// CTA tile: 128 points x 128 out-dims, 3 streams, K=256 in 4 chunks of 64.
// smem: [0] tmem ptr, [8] mbar, [512] bias(128 f32),
//       [1024]          sB tiles: 8 x 16KB  (half h, chunk c) -> idx h*4+c
//       [1024+131072]   sA tiles: 6 x 16KB  (stream s, half h) -> idx s*2+h
#define OFF_BIAS 512
#define OFF_B    1024
#define OFF_A    (1024 + 8 * 16384)
#define SMEM_BYTES (OFF_A + 6 * 16384)   // 230400

__global__ void __launch_bounds__(256, 1)
mma_layer_kernel(const uint32_t* __restrict__ Ain,
                 const uint32_t* __restrict__ Wpk,
                 const float* __restrict__ bias,
                 uint32_t* __restrict__ Aout,
                 int last)
{
#if HAS_TCGEN05
    extern __shared__ char smem[];
    const uint32_t sbase = smem_u32(smem);
    const int tid = threadIdx.x;
    const int wid = tid >> 5;
    const int pt  = blockIdx.x >> 1;       // point tile
    const int ch  = blockIdx.x & 1;        // col half
    const size_t rowBase = (size_t)pt * 128;

    if (wid == 0) { tc_alloc(sbase, 512); tc_relinq(); }
    if (tid == 0) mbar_init(sbase + 8, 1);

    if (tid < 128)
        *(float*)(smem + OFF_BIAS + tid * 4) = bias[ch * 128 + tid];

    // load full-K W tiles (8 x 16KB): rows = out dims (128), K-major 64-bf16 rows
    #pragma unroll 4
    for (int idx = tid; idx < 8192; idx += 256) {
        int nrow = idx >> 6;
        int q    = idx & 63;
        int k0   = q << 2;
        int c    = k0 >> 6;
        int kk   = k0 & 63;
        uint4 v = *(const uint4*)(Wpk + (size_t)(ch * 128 + nrow) * HDIM + k0);
        uint32_t h0 = __byte_perm(v.x, v.y, 0x5410);
        uint32_t h1 = __byte_perm(v.z, v.w, 0x5410);
        uint32_t l0 = __byte_perm(v.x, v.y, 0x7632);
        uint32_t l1 = __byte_perm(v.z, v.w, 0x7632);
        uint32_t sw = SWZ128(nrow * 128 + kk * 2);
        *(uint2*)(smem + OFF_B + (0 * 4 + c) * 16384 + sw) = make_uint2(h0, h1);
        *(uint2*)(smem + OFF_B + (4 + c) * 16384 + sw)     = make_uint2(l0, l1);
    }
    __syncthreads();
    const uint32_t tmem = *(const uint32_t*)smem;

    // K loop: 4 chunks of 64; per chunk 3 streams x 3 products x 4 ksteps
    for (int c = 0; c < 4; c++) {
        #pragma unroll 4
        for (int idx = tid; idx < 6144; idx += 256) {
            int s   = idx >> 11;           // stream
            int rem = idx & 2047;
            int r   = rem >> 4;            // row 0..127
            int q   = rem & 15;
            int kk  = q << 2;
            uint4 v = *(const uint4*)(Ain + (size_t)s * PLANE +
                                      (rowBase + r) * HDIM + c * 64 + kk);
            uint32_t h0 = __byte_perm(v.x, v.y, 0x5410);
            uint32_t h1 = __byte_perm(v.z, v.w, 0x5410);
            uint32_t l0 = __byte_perm(v.x, v.y, 0x7632);
            uint32_t l1 = __byte_perm(v.z, v.w, 0x7632);
            uint32_t sw = SWZ128(r * 128 + kk * 2);
            *(uint2*)(smem + OFF_A + (s * 2 + 0) * 16384 + sw) = make_uint2(h0, h1);
            *(uint2*)(smem + OFF_A + (s * 2 + 1) * 16384 + sw) = make_uint2(l0, l1);
        }
        __syncthreads();

        if (wid == 0) {
            fence_async();
            if (elect_one()) {
                #pragma unroll
                for (int s = 0; s < 3; s++) {
                    uint32_t dts = tmem + s * 128;
                    #pragma unroll
                    for (int prod = 0; prod < 3; prod++) {
                        int ha = (prod == 2) ? 1 : 0;          // (0,0) (0,1) (1,0)
                        int hb = (prod == 1) ? 1 : 0;
                        uint64_t ad = mk_desc(sbase + OFF_A + (s * 2 + ha) * 16384);
                        uint64_t bd = mk_desc(sbase + OFF_B + (hb * 4 + c) * 16384);
                        #pragma unroll
                        for (int ks = 0; ks < 4; ks++) {
                            uint32_t en = !(c == 0 && prod == 0 && ks == 0);
                            mma_f16_ss(dts, ad + ks * 2, bd + ks * 2, en);
                        }
                    }
                }
                tc_commit(sbase + 8);
            }
        }
        mbar_wait(sbase + 8, c & 1);
        __syncthreads();
    }
    tc_fence_after();

    // epilogue: warp w -> rows (w&3)*32+lane, col half (w>>2)
    {
        const int sub  = wid & 3;
        const int half = wid >> 2;
        const int lane = tid & 31;
        const size_t grow = rowBase + sub * 32 + lane;

        #pragma unroll
        for (int cb = 0; cb < 8; cb++) {
            int colbase = half * 64 + cb * 8;
            uint32_t rz[8], rp[8], rq[8];
            ldtm_x8(rz, tmem + 0   + colbase);
            ldtm_x8(rp, tmem + 128 + colbase);
            ldtm_x8(rq, tmem + 256 + colbase);
            tc_wait_ld();

            uint32_t o0[8], o1[8], o2[8];
            #pragma unroll
            for (int j = 0; j < 8; j++) {
                float bv  = *(const float*)(smem + OFF_BIAS + (colbase + j) * 4);
                float z   = __uint_as_float(rz[j]) + bv;
                float zp  = __uint_as_float(rp[j]);
                float zpp = __uint_as_float(rq[j]);
                float a   = tanhf(z);
                float g   = 1.0f - a * a;
                float hp  = g * zp;
                float hpp = fmaf(g, zpp, -2.0f * a * zp * hp);
                if (last) {
                    o0[j] = __float_as_uint(a);
                    o1[j] = __float_as_uint(hp);
                    o2[j] = __float_as_uint(hpp);
                } else {
                    o0[j] = pack_hl(a);
                    o1[j] = pack_hl(hp);
                    o2[j] = pack_hl(hpp);
                }
            }
            size_t base = grow * HDIM + ch * 128 + colbase;
            *(uint4*)(Aout + base)                 = make_uint4(o0[0], o0[1], o0[2], o0[3]);
            *(uint4*)(Aout + base + 4)             = make_uint4(o0[4], o0[5], o0[6], o0[7]);
            *(uint4*)(Aout + PLANE + base)         = make_uint4(o1[0], o1[1], o1[2], o1[3]);
            *(uint4*)(Aout + PLANE + base + 4)     = make_uint4(o1[4], o1[5], o1[6], o1[7]);
            *(uint4*)(Aout + 2 * PLANE + base)     = make_uint4(o2[0], o2[1], o2[2], o2[3]);
            *(uint4*)(Aout + 2 * PLANE + base + 4) = make_uint4(o2[4], o2[5], o2[6], o2[7]);
        }
    }

    __syncthreads();
    if (wid == 0) tc_dealloc(tmem, 512);
#endif  // HAS_TCGEN05
}

// ---------------- final head -------------------------------------------------
__global__ void final_kernel(const float* __restrict__ A,   // fp32 planes
                             const float* __restrict__ W4,
                             const float* __restrict__ b4,
                             const float* __restrict__ lgr,
                             const float* __restrict__ lcc,
                             const float* __restrict__ lil,
                             const float* __restrict__ tgt_mean,
                             const float* __restrict__ tgt_std,
                             float* __restrict__ out, int n)
{
    int warp = (blockIdx.x * blockDim.x + threadIdx.x) >> 5;
    int ln   = threadIdx.x & 31;
    if (warp >= n) return;

    float sums[3];
    #pragma unroll
    for (int s = 0; s < 3; s++) {
        const float* base = A + (size_t)s * PLANE + (size_t)warp * HDIM;
        float acc = 0.0f;
        #pragma unroll
        for (int k = ln; k < HDIM; k += 32)
            acc = fmaf(base[k], __ldg(W4 + k), acc);
        #pragma unroll
        for (int off = 16; off > 0; off >>= 1)
            acc += __shfl_xor_sync(0xffffffffu, acc, off);
        sums[s] = acc;
    }

    if (ln == 0) {
        float ts = tgt_std[0];
        float tm = tgt_mean[0];
        float r_ = expf(-lgr[0]);
        float Kc = 0.2f + 0.8f / (1.0f + expf(-lcc[0]));
        float Cc = 0.1f / (1.0f + expf(-lil[0]));

        float U   = (sums[0] + b4[0]) * ts + tm;
        float Ut  = sums[1] * ts;
        float Utt = sums[2] * ts;

        float d  = (U - Cc) / (Kc - Cc);
        float G  = r_ * (U - Cc) * (1.0f - d);
        float F  = Ut - G;
        float Gt = r_ * Ut * (1.0f - 2.0f * d);
        float Ft = Utt - Gt;

        out[warp]         = U;
        out[n + warp]     = F;
        out[2 * n + warp] = Ft;
    }
}

// ---------------------------------------------------------------------------
extern "C" void kernel_launch(void* const* d_in, const int* in_sizes, int n_in,
                              void* d_out, int out_size)
{
    const float* inputs  = (const float*)d_in[0];
    const float* W0      = (const float*)d_in[1];
    const float* b0      = (const float*)d_in[2];
    const float* W1      = (const float*)d_in[3];
    const float* b1      = (const float*)d_in[4];
    const float* W2      = (const float*)d_in[5];
    const float* b2      = (const float*)d_in[6];
    const float* W3      = (const float*)d_in[7];
    const float* b3      = (const float*)d_in[8];
    const float* W4      = (const float*)d_in[9];
    const float* b4      = (const float*)d_in[10];
    const float* lgr     = (const float*)d_in[11];
    const float* lcc     = (const float*)d_in[12];
    const float* lil     = (const float*)d_in[13];
    const float* in_mean = (const float*)d_in[14];
    const float* in_std  = (const float*)d_in[15];
    const float* tgt_mean= (const float*)d_in[16];
    const float* tgt_std = (const float*)d_in[17];

    int n = in_sizes[0] / 2;
    if (n > NPTS) n = NPTS;

    uint32_t *actA, *actB, *wpk;
    cudaGetSymbolAddress((void**)&actA, g_actA);
    cudaGetSymbolAddress((void**)&actB, g_actB);
    cudaGetSymbolAddress((void**)&wpk, g_Wpk);

    cudaFuncSetAttribute(mma_layer_kernel,
                         cudaFuncAttributeMaxDynamicSharedMemorySize, SMEM_BYTES);

    pack_weights_kernel<<<(3 * HDIM * HDIM + 255) / 256, 256>>>(W1, W2, W3, wpk);
    layer0_kernel<<<(n * HDIM + 255) / 256, 256>>>(inputs, W0, b0, in_mean, in_std, actA, n);

    int tiles = (n / 128) * 2;
    mma_layer_kernel<<<tiles, 256, SMEM_BYTES>>>(actA, wpk,                   b1, actB, 0);
    mma_layer_kernel<<<tiles, 256, SMEM_BYTES>>>(actB, wpk + HDIM * HDIM,     b2, actA, 0);
    mma_layer_kernel<<<tiles, 256, SMEM_BYTES>>>(actA, wpk + 2 * HDIM * HDIM, b3, actB, 1);

    final_kernel<<<(n + 7) / 8, 256>>>((const float*)actB, W4, b4, lgr, lcc, lil,
                                       tgt_mean, tgt_std, (float*)d_out, n);
}

// round 4
// speedup vs baseline: 5.0953x; 1.9015x over previous
#include <cuda_runtime.h>
#include <cuda_bf16.h>
#include <math.h>
#include <stdint.h>

// ---------------------------------------------------------------------------
// CapacityNN on tcgen05, R4: activations live in gmem PRE-SWIZZLED as separate
// hi/lo bf16 SW128 16KB MMA tiles. Layer kernel ingests them with
// cp.async.bulk through a depth-3 mbarrier pipeline (no LDG/STS staging).
// Layer 3's epilogue fuses the W4 head (partial dots + atomicAdd), removing
// the fp32 activation round-trip. Split-bf16 (hi/lo, 3 products) = ~fp32.
// ---------------------------------------------------------------------------

#if defined(__CUDA_ARCH_FEAT_SM103_ALL) || \
    (defined(__CUDA_ARCH_SPECIFIC__) && (__CUDA_ARCH_SPECIFIC__ == 1030))
#define HAS_TCGEN05 1
#else
#define HAS_TCGEN05 0
#endif

#define NPTS 65536
#define HDIM 256
#define PLANE ((size_t)NPTS * HDIM)

// activation buffers: 512 pt-tiles x 4 chunks x 3 streams x 2 halves x 16KB
__device__ __align__(128) uint32_t g_actA[3 * PLANE];
__device__ __align__(128) uint32_t g_actB[3 * PLANE];
__device__ __align__(128) uint32_t g_Wpk[3 * HDIM * HDIM];
__device__ float g_head[3 * NPTS];

// byte offset of block (pt-tile, k-chunk, stream, half)
__host__ __device__ __forceinline__ size_t blk_off(int pt, int c, int s, int h) {
    return ((((size_t)pt * 4 + c) * 3 + s) * 2 + h) * 16384;
}

// ---------------- PTX helpers ------------------------------------------------
__device__ __forceinline__ uint32_t smem_u32(const void* p) {
    uint32_t a;
    asm("{ .reg .u64 t; cvta.to.shared.u64 t, %1; cvt.u32.u64 %0, t; }"
        : "=r"(a) : "l"(p));
    return a;
}
#define SWZ128(o) ((o) ^ (((o) >> 3) & 0x70))

static constexpr uint64_t DESC_BASE_SW128 =
    (2ULL << 61) | (1ULL << 46) | (64ULL << 32) | (1ULL << 16);
__device__ __forceinline__ uint64_t mk_desc(uint32_t addr) {
    return DESC_BASE_SW128 | ((uint64_t)(addr >> 4) & 0x3FFF);
}

// idesc: dtype=F32, atype=BF16, btype=BF16, N=128, M=128 (cta_group::1)
#define MMA_IDESC 0x08200490u

__device__ __forceinline__ void mma_f16_ss(uint32_t d, uint64_t a, uint64_t b,
                                           uint32_t en) {
#if HAS_TCGEN05
    asm volatile(
        "{\n\t.reg .pred p;\n\tsetp.ne.u32 p, %4, 0;\n\t"
        "tcgen05.mma.cta_group::1.kind::f16 [%0], %1, %2, %3, {%5,%5,%5,%5}, p;\n\t}"
        :: "r"(d), "l"(a), "l"(b), "r"(MMA_IDESC), "r"(en), "r"(0u)
        : "memory");
#endif
}
__device__ __forceinline__ void tc_alloc(uint32_t sm, uint32_t n) {
#if HAS_TCGEN05
    asm volatile("tcgen05.alloc.cta_group::1.sync.aligned.shared::cta.b32 [%0], %1;"
                 :: "r"(sm), "r"(n) : "memory");
#endif
}
__device__ __forceinline__ void tc_relinq() {
#if HAS_TCGEN05
    asm volatile("tcgen05.relinquish_alloc_permit.cta_group::1.sync.aligned;");
#endif
}
__device__ __forceinline__ void tc_dealloc(uint32_t t, uint32_t n) {
#if HAS_TCGEN05
    asm volatile("tcgen05.dealloc.cta_group::1.sync.aligned.b32 %0, %1;"
                 :: "r"(t), "r"(n));
#endif
}
__device__ __forceinline__ void tc_commit(uint32_t mb) {
#if HAS_TCGEN05
    asm volatile("tcgen05.commit.cta_group::1.mbarrier::arrive::one.shared::cluster.b64 [%0];"
                 :: "r"(mb) : "memory");
#endif
}
__device__ __forceinline__ void tc_fence_after() {
#if HAS_TCGEN05
    asm volatile("tcgen05.fence::after_thread_sync;" ::: "memory");
#endif
}
__device__ __forceinline__ void tc_wait_ld() {
#if HAS_TCGEN05
    asm volatile("tcgen05.wait::ld.sync.aligned;" ::: "memory");
#endif
}
__device__ __forceinline__ void mbar_init(uint32_t mb, uint32_t n) {
    asm volatile("mbarrier.init.shared.b64 [%0], %1;" :: "r"(mb), "r"(n) : "memory");
}
__device__ __forceinline__ void mbar_expect_tx(uint32_t mb, uint32_t bytes) {
    asm volatile("mbarrier.arrive.expect_tx.shared.b64 _, [%0], %1;"
                 :: "r"(mb), "r"(bytes) : "memory");
}
__device__ __forceinline__ void fence_async() {
    asm volatile("fence.proxy.async.shared::cta;" ::: "memory");
}
__device__ __forceinline__ void bulk_copy_g2s(uint32_t dst, const void* src,
                                              uint32_t bytes, uint32_t mb) {
#if HAS_TCGEN05
    asm volatile("cp.async.bulk.shared::cluster.global.mbarrier::complete_tx::bytes "
                 "[%0], [%1], %2, [%3];"
                 :: "r"(dst), "l"(src), "r"(bytes), "r"(mb) : "memory");
#endif
}
__device__ __forceinline__ void mbar_wait(uint32_t mb, uint32_t parity) {
    uint32_t done;
    asm volatile(
        "{\n\t.reg .pred p;\n\t"
        "mbarrier.try_wait.parity.acquire.cta.shared::cta.b64 p, [%1], %2;\n\t"
        "selp.b32 %0, 1, 0, p;\n\t}"
        : "=r"(done) : "r"(mb), "r"(parity) : "memory");
    if (!done) {
        asm volatile(
            "{\n\t.reg .pred P1;\n\t"
            "WL_%=:\n\t"
            "mbarrier.try_wait.parity.acquire.cta.shared::cta.b64 P1, [%0], %1, 0x989680;\n\t"
            "@P1 bra.uni WD_%=;\n\t"
            "bra.uni WL_%=;\n\t"
            "WD_%=:\n\t}"
            :: "r"(mb), "r"(parity) : "memory");
    }
}
__device__ __forceinline__ void ldtm_x8(uint32_t* r, uint32_t addr) {
#if HAS_TCGEN05
    asm volatile("tcgen05.ld.sync.aligned.32x32b.x8.b32 "
                 "{%0,%1,%2,%3,%4,%5,%6,%7}, [%8];"
                 : "=r"(r[0]), "=r"(r[1]), "=r"(r[2]), "=r"(r[3]),
                   "=r"(r[4]), "=r"(r[5]), "=r"(r[6]), "=r"(r[7])
                 : "r"(addr));
#else
    for (int i = 0; i < 8; i++) r[i] = 0;
#endif
}

__device__ __forceinline__ uint32_t pack_hl(float x) {
    __nv_bfloat16 h = __float2bfloat16(x);
    float hf = __bfloat162float(h);
    __nv_bfloat16 l = __float2bfloat16(x - hf);
    return (uint32_t)__bfloat16_as_ushort(h) |
           ((uint32_t)__bfloat16_as_ushort(l) << 16);
}
__device__ __forceinline__ uint16_t bf_hi(float x) {
    return __bfloat16_as_ushort(__float2bfloat16(x));
}
__device__ __forceinline__ uint16_t bf_lo(float x) {
    float hf = __bfloat162float(__float2bfloat16(x));
    return __bfloat16_as_ushort(__float2bfloat16(x - hf));
}

// ---------------- weight packing (hi|lo u32, K-major rows) -------------------
__global__ void pack_weights_kernel(const float* __restrict__ W1,
                                    const float* __restrict__ W2,
                                    const float* __restrict__ W3,
                                    uint32_t* __restrict__ out) {
    int idx = blockIdx.x * blockDim.x + threadIdx.x;
    if (idx >= 3 * HDIM * HDIM) return;
    const float* W = (idx < HDIM * HDIM) ? W1
                     : (idx < 2 * HDIM * HDIM) ? W2 : W3;
    out[idx] = pack_hl(W[idx % (HDIM * HDIM)]);
}

// ---------------- layer 0: write swizzled hi/lo planes + zero head -----------
__global__ void layer0_kernel(const float* __restrict__ in,
                              const float* __restrict__ W0,
                              const float* __restrict__ b0,
                              const float* __restrict__ in_mean,
                              const float* __restrict__ in_std,
                              uint8_t* __restrict__ H,
                              float* __restrict__ head, int n)
{
    int gid = blockIdx.x * blockDim.x + threadIdx.x;
    if (gid < 3 * n) head[gid] = 0.0f;
    if (gid >= n * 128) return;
    int p = gid >> 7;
    int q = gid & 127;          // output pair index: o = 2q, 2q+1
    int o = q << 1;

    float s  = in[p * 2 + 0];
    float tt = in[p * 2 + 1];
    float sn = (s  - in_mean[0]) / (in_std[0] + 1e-8f);
    float tn = (tt - in_mean[1]) / (in_std[1] + 1e-8f);

    float v[3][2];
    #pragma unroll
    for (int e = 0; e < 2; e++) {
        float w0 = W0[(o + e) * 2 + 0];
        float w1 = W0[(o + e) * 2 + 1];
        float z  = fmaf(w0, sn, fmaf(w1, tn, b0[o + e]));
        float a   = tanhf(z);
        float g   = 1.0f - a * a;
        float hp  = g * w1;
        float hpp = -2.0f * a * w1 * hp;
        v[0][e] = a; v[1][e] = hp; v[2][e] = hpp;
    }

    int pt = p >> 7;
    int r  = p & 127;
    int c  = q >> 5;
    int kk = (q & 31) << 1;                 // even k within chunk
    uint32_t sw = SWZ128((uint32_t)(r * 128 + kk * 2));

    #pragma unroll
    for (int st = 0; st < 3; st++) {
        uint32_t hi = (uint32_t)bf_hi(v[st][0]) | ((uint32_t)bf_hi(v[st][1]) << 16);
        uint32_t lo = (uint32_t)bf_lo(v[st][0]) | ((uint32_t)bf_lo(v[st][1]) << 16);
        *(uint32_t*)(H + blk_off(pt, c, st, 0) + sw) = hi;
        *(uint32_t*)(H + blk_off(pt, c, st, 1) + sw) = lo;
    }
}

// ---------------- tcgen05 hidden layer ---------------------------------------
// smem map (bytes):
//   [0]     tmem ptr
//   [8..64) mbarriers: full[3]@8,16,24  done[3]@32,40,48  epi@56
//   [1024)  bias 128 f32
//   [1536)  W4 tile 128 f32 (last layer only)
//   [2048)  sB: 8 x 16KB  (half h, chunk c) -> idx h*4+c
//   [133120) A ring: 3 slots x 32KB (hi block + lo block)
#define MB_FULL(i) (8u  + (uint32_t)(i) * 8u)
#define MB_DONE(i) (32u + (uint32_t)(i) * 8u)
#define MB_EPI     56u
#define OFF_BIAS 1024
#define OFF_W4   1536
#define OFF_B    2048
#define OFF_A    (2048 + 8 * 16384)
#define SMEM_BYTES (OFF_A + 3 * 32768)   // 231424

__global__ void __launch_bounds__(256, 1)
mma_layer_kernel(const uint8_t* __restrict__ Ain,
                 const uint32_t* __restrict__ Wpk,
                 const float* __restrict__ bias,
                 const float* __restrict__ W4,
                 uint8_t* __restrict__ Aout,
                 float* __restrict__ head,
                 int last)
{
#if HAS_TCGEN05
    extern __shared__ char smem[];
    const uint32_t sbase = smem_u32(smem);
    const int tid = threadIdx.x;
    const int wid = tid >> 5;
    const int lane = tid & 31;
    const int pt  = blockIdx.x >> 1;       // point tile
    const int ch  = blockIdx.x & 1;        // col half
    const size_t rowBase = (size_t)pt * 128;

    if (wid == 0) { tc_alloc(sbase, 512); tc_relinq(); }
    if (tid == 0) {
        #pragma unroll
        for (int i = 0; i < 3; i++) { mbar_init(MB_FULL(i) + sbase, 1);
                                      mbar_init(MB_DONE(i) + sbase, 1); }
        mbar_init(sbase + MB_EPI, 1);
    }

    if (tid < 128) {
        *(float*)(smem + OFF_BIAS + tid * 4) = bias[ch * 128 + tid];
        if (last) *(float*)(smem + OFF_W4 + tid * 4) = W4[ch * 128 + tid];
    }

    // stage W (full K, hi+lo): 8 x 16KB SW128 tiles
    #pragma unroll 4
    for (int idx = tid; idx < 8192; idx += 256) {
        int nrow = idx >> 6;
        int q    = idx & 63;
        int k0   = q << 2;
        int c    = k0 >> 6;
        int kk   = k0 & 63;
        uint4 v = *(const uint4*)(Wpk + (size_t)(ch * 128 + nrow) * HDIM + k0);
        uint32_t h0 = __byte_perm(v.x, v.y, 0x5410);
        uint32_t h1 = __byte_perm(v.z, v.w, 0x5410);
        uint32_t l0 = __byte_perm(v.x, v.y, 0x7632);
        uint32_t l1 = __byte_perm(v.z, v.w, 0x7632);
        uint32_t sw = SWZ128(nrow * 128 + kk * 2);
        *(uint2*)(smem + OFF_B + c * 16384 + sw)       = make_uint2(h0, h1);
        *(uint2*)(smem + OFF_B + (4 + c) * 16384 + sw) = make_uint2(l0, l1);
    }
    __syncthreads();
    const uint32_t tmem = *(const uint32_t*)smem;

    // producer: warp 1 lane 0 issues bulk copies through the depth-3 ring
    if (wid == 1 && lane == 0) {
        const uint8_t* src = Ain + blk_off(pt, 0, 0, 0);
        #pragma unroll 1
        for (int g = 0; g < 12; g++) {
            int slot = g % 3, rg = g / 3;
            if (rg > 0) mbar_wait(sbase + MB_DONE(slot), (rg - 1) & 1);
            mbar_expect_tx(sbase + MB_FULL(slot), 32768);
            bulk_copy_g2s(sbase + OFF_A + slot * 32768,
                          src + (size_t)g * 32768, 32768,
                          sbase + MB_FULL(slot));
        }
    }

    // MMA issuer: warp 0 lane 0
    if (wid == 0 && lane == 0) {
        fence_async();
        #pragma unroll 1
        for (int g = 0; g < 12; g++) {
            int slot = g % 3;
            int c = g / 3, s = g % 3;
            mbar_wait(sbase + MB_FULL(slot), c & 1);
            uint32_t dts = tmem + s * 128;
            #pragma unroll
            for (int prod = 0; prod < 3; prod++) {
                int ha = (prod == 2) ? 1 : 0;
                int hb = (prod == 1) ? 1 : 0;
                uint64_t ad = mk_desc(sbase + OFF_A + slot * 32768 + ha * 16384);
                uint64_t bd = mk_desc(sbase + OFF_B + (hb * 4 + c) * 16384);
                #pragma unroll
                for (int ks = 0; ks < 4; ks++) {
                    uint32_t en = !(c == 0 && prod == 0 && ks == 0);
                    mma_f16_ss(dts, ad + ks * 2, bd + ks * 2, en);
                }
            }
            tc_commit(sbase + MB_DONE(slot));
        }
        tc_commit(sbase + MB_EPI);
    }

    // all threads wait for all MMAs, then epilogue
    mbar_wait(sbase + MB_EPI, 0);
    tc_fence_after();

    {
        const int sub  = wid & 3;
        const int half = wid >> 2;
        const size_t r = sub * 32 + lane;       // row within tile
        const int c_out = ch * 2 + half;        // K-chunk index in next layer
        float acc0 = 0.f, acc1 = 0.f, acc2 = 0.f;

        #pragma unroll
        for (int cb = 0; cb < 8; cb++) {
            int colbase = half * 64 + cb * 8;
            uint32_t rz[8], rp[8], rq[8];
            ldtm_x8(rz, tmem + 0   + colbase);
            ldtm_x8(rp, tmem + 128 + colbase);
            ldtm_x8(rq, tmem + 256 + colbase);
            tc_wait_ld();

            float va[8], vp[8], vq[8];
            #pragma unroll
            for (int j = 0; j < 8; j++) {
                float bv  = *(const float*)(smem + OFF_BIAS + (colbase + j) * 4);
                float z   = __uint_as_float(rz[j]) + bv;
                float zp  = __uint_as_float(rp[j]);
                float zpp = __uint_as_float(rq[j]);
                float a   = tanhf(z);
                float g   = 1.0f - a * a;
                float hp  = g * zp;
                float hpp = fmaf(g, zpp, -2.0f * a * zp * hp);
                va[j] = a; vp[j] = hp; vq[j] = hpp;
            }

            if (last) {
                #pragma unroll
                for (int j = 0; j < 8; j++) {
                    float w4 = *(const float*)(smem + OFF_W4 + (colbase + j) * 4);
                    acc0 = fmaf(w4, va[j], acc0);
                    acc1 = fmaf(w4, vp[j], acc1);
                    acc2 = fmaf(w4, vq[j], acc2);
                }
            } else {
                uint32_t sw = SWZ128((uint32_t)(r * 128 + cb * 16));
                uint32_t hi[3][4], lo[3][4];
                #pragma unroll
                for (int j = 0; j < 4; j++) {
                    hi[0][j] = (uint32_t)bf_hi(va[2*j]) | ((uint32_t)bf_hi(va[2*j+1]) << 16);
                    lo[0][j] = (uint32_t)bf_lo(va[2*j]) | ((uint32_t)bf_lo(va[2*j+1]) << 16);
                    hi[1][j] = (uint32_t)bf_hi(vp[2*j]) | ((uint32_t)bf_hi(vp[2*j+1]) << 16);
                    lo[1][j] = (uint32_t)bf_lo(vp[2*j]) | ((uint32_t)bf_lo(vp[2*j+1]) << 16);
                    hi[2][j] = (uint32_t)bf_hi(vq[2*j]) | ((uint32_t)bf_hi(vq[2*j+1]) << 16);
                    lo[2][j] = (uint32_t)bf_lo(vq[2*j]) | ((uint32_t)bf_lo(vq[2*j+1]) << 16);
                }
                #pragma unroll
                for (int st = 0; st < 3; st++) {
                    *(uint4*)(Aout + blk_off(pt, c_out, st, 0) + sw) =
                        make_uint4(hi[st][0], hi[st][1], hi[st][2], hi[st][3]);
                    *(uint4*)(Aout + blk_off(pt, c_out, st, 1) + sw) =
                        make_uint4(lo[st][0], lo[st][1], lo[st][2], lo[st][3]);
                }
            }
        }
        if (last) {
            size_t p = rowBase + r;
            atomicAdd(head + p,             acc0);
            atomicAdd(head + NPTS + p,      acc1);
            atomicAdd(head + 2 * NPTS + p,  acc2);
        }
    }

    __syncthreads();
    if (wid == 0) tc_dealloc(tmem, 512);
#endif  // HAS_TCGEN05
}

// ---------------- final: logistic terms from head sums -----------------------
__global__ void final2_kernel(const float* __restrict__ head,
                              const float* __restrict__ b4,
                              const float* __restrict__ lgr,
                              const float* __restrict__ lcc,
                              const float* __restrict__ lil,
                              const float* __restrict__ tgt_mean,
                              const float* __restrict__ tgt_std,
                              float* __restrict__ out, int n)
{
    int i = blockIdx.x * blockDim.x + threadIdx.x;
    if (i >= n) return;

    float ts = tgt_std[0];
    float tm = tgt_mean[0];
    float r_ = expf(-lgr[0]);
    float Kc = 0.2f + 0.8f / (1.0f + expf(-lcc[0]));
    float Cc = 0.1f / (1.0f + expf(-lil[0]));

    float U   = (head[i] + b4[0]) * ts + tm;
    float Ut  = head[n + i] * ts;
    float Utt = head[2 * n + i] * ts;

    float d  = (U - Cc) / (Kc - Cc);
    float G  = r_ * (U - Cc) * (1.0f - d);
    float F  = Ut - G;
    float Gt = r_ * Ut * (1.0f - 2.0f * d);
    float Ft = Utt - Gt;

    out[i]         = U;
    out[n + i]     = F;
    out[2 * n + i] = Ft;
}

// ---------------------------------------------------------------------------
extern "C" void kernel_launch(void* const* d_in, const int* in_sizes, int n_in,
                              void* d_out, int out_size)
{
    const float* inputs  = (const float*)d_in[0];
    const float* W0      = (const float*)d_in[1];
    const float* b0      = (const float*)d_in[2];
    const float* W1      = (const float*)d_in[3];
    const float* b1      = (const float*)d_in[4];
    const float* W2      = (const float*)d_in[5];
    const float* b2      = (const float*)d_in[6];
    const float* W3      = (const float*)d_in[7];
    const float* b3      = (const float*)d_in[8];
    const float* W4      = (const float*)d_in[9];
    const float* b4      = (const float*)d_in[10];
    const float* lgr     = (const float*)d_in[11];
    const float* lcc     = (const float*)d_in[12];
    const float* lil     = (const float*)d_in[13];
    const float* in_mean = (const float*)d_in[14];
    const float* in_std  = (const float*)d_in[15];
    const float* tgt_mean= (const float*)d_in[16];
    const float* tgt_std = (const float*)d_in[17];

    int n = in_sizes[0] / 2;
    if (n > NPTS) n = NPTS;

    uint8_t *actA, *actB;
    uint32_t *wpk;
    float *head;
    cudaGetSymbolAddress((void**)&actA, g_actA);
    cudaGetSymbolAddress((void**)&actB, g_actB);
    cudaGetSymbolAddress((void**)&wpk, g_Wpk);
    cudaGetSymbolAddress((void**)&head, g_head);

    cudaFuncSetAttribute(mma_layer_kernel,
                         cudaFuncAttributeMaxDynamicSharedMemorySize, SMEM_BYTES);

    pack_weights_kernel<<<(3 * HDIM * HDIM + 255) / 256, 256>>>(W1, W2, W3, wpk);
    layer0_kernel<<<(n * 128 + 255) / 256, 256>>>(inputs, W0, b0, in_mean, in_std,
                                                  actA, head, n);

    int tiles = (n / 128) * 2;
    mma_layer_kernel<<<tiles, 256, SMEM_BYTES>>>(actA, wpk,                   b1, W4, actB, head, 0);
    mma_layer_kernel<<<tiles, 256, SMEM_BYTES>>>(actB, wpk + HDIM * HDIM,     b2, W4, actA, head, 0);
    mma_layer_kernel<<<tiles, 256, SMEM_BYTES>>>(actA, wpk + 2 * HDIM * HDIM, b3, W4, actB, head, 1);

    final2_kernel<<<(n + 255) / 256, 256>>>(head, b4, lgr, lcc, lil,
                                            tgt_mean, tgt_std, (float*)d_out, n);
}

// round 5
// speedup vs baseline: 5.6504x; 1.1090x over previous
#include <cuda_runtime.h>
#include <cuda_bf16.h>
#include <math.h>
#include <stdint.h>

// ---------------------------------------------------------------------------
// CapacityNN on tcgen05, R5: persistent layer kernel (grid=148). Each CTA owns
// one column half (ch) and ~7 point-tiles; W staged once per CTA. Warp roles:
//   warps 0-7: W staging + TMEM epilogue (tanh chain rule, pack, store)
//   warp 8   : MMA issuer (144 tcgen05 dispatches / tile)
//   warp 9   : cp.async.bulk producer streaming A groups through depth-3 ring
// Split-bf16 (hi/lo, 3 products) = ~fp32 accuracy. Layer-3 epilogue fuses the
// W4 head via atomicAdd partial dots.
// ---------------------------------------------------------------------------

#if defined(__CUDA_ARCH_FEAT_SM103_ALL) || \
    (defined(__CUDA_ARCH_SPECIFIC__) && (__CUDA_ARCH_SPECIFIC__ == 1030))
#define HAS_TCGEN05 1
#else
#define HAS_TCGEN05 0
#endif

#define NPTS 65536
#define HDIM 256
#define PLANE ((size_t)NPTS * HDIM)
#define NTILES_PT 512                     // point tiles (128 pts each)
#define TILE_BYTES 393216                 // 12 groups x 32KB

__device__ __align__(128) uint32_t g_actA[3 * PLANE];
__device__ __align__(128) uint32_t g_actB[3 * PLANE];
__device__ __align__(128) uint32_t g_Wpk[3 * HDIM * HDIM];
__device__ float g_head[3 * NPTS];

// byte offset of block (pt-tile, k-chunk c, stream s, half h)
__host__ __device__ __forceinline__ size_t blk_off(int pt, int c, int s, int h) {
    return ((((size_t)pt * 4 + c) * 3 + s) * 2 + h) * 16384;
}

// ---------------- PTX helpers ------------------------------------------------
__device__ __forceinline__ uint32_t smem_u32(const void* p) {
    uint32_t a;
    asm("{ .reg .u64 t; cvta.to.shared.u64 t, %1; cvt.u32.u64 %0, t; }"
        : "=r"(a) : "l"(p));
    return a;
}
#define SWZ128(o) ((o) ^ (((o) >> 3) & 0x70))

static constexpr uint64_t DESC_BASE_SW128 =
    (2ULL << 61) | (1ULL << 46) | (64ULL << 32) | (1ULL << 16);
__device__ __forceinline__ uint64_t mk_desc(uint32_t addr) {
    return DESC_BASE_SW128 | ((uint64_t)(addr >> 4) & 0x3FFF);
}

#define MMA_IDESC 0x08200490u   // F32 accum, BF16xBF16, M=128, N=128

__device__ __forceinline__ void mma_f16_ss(uint32_t d, uint64_t a, uint64_t b,
                                           uint32_t en) {
#if HAS_TCGEN05
    asm volatile(
        "{\n\t.reg .pred p;\n\tsetp.ne.u32 p, %4, 0;\n\t"
        "tcgen05.mma.cta_group::1.kind::f16 [%0], %1, %2, %3, {%5,%5,%5,%5}, p;\n\t}"
        :: "r"(d), "l"(a), "l"(b), "r"(MMA_IDESC), "r"(en), "r"(0u)
        : "memory");
#endif
}
__device__ __forceinline__ void tc_alloc(uint32_t sm, uint32_t n) {
#if HAS_TCGEN05
    asm volatile("tcgen05.alloc.cta_group::1.sync.aligned.shared::cta.b32 [%0], %1;"
                 :: "r"(sm), "r"(n) : "memory");
#endif
}
__device__ __forceinline__ void tc_relinq() {
#if HAS_TCGEN05
    asm volatile("tcgen05.relinquish_alloc_permit.cta_group::1.sync.aligned;");
#endif
}
__device__ __forceinline__ void tc_dealloc(uint32_t t, uint32_t n) {
#if HAS_TCGEN05
    asm volatile("tcgen05.dealloc.cta_group::1.sync.aligned.b32 %0, %1;"
                 :: "r"(t), "r"(n));
#endif
}
__device__ __forceinline__ void tc_commit(uint32_t mb) {
#if HAS_TCGEN05
    asm volatile("tcgen05.commit.cta_group::1.mbarrier::arrive::one.shared::cluster.b64 [%0];"
                 :: "r"(mb) : "memory");
#endif
}
__device__ __forceinline__ void tc_fence_after() {
#if HAS_TCGEN05
    asm volatile("tcgen05.fence::after_thread_sync;" ::: "memory");
#endif
}
__device__ __forceinline__ void tc_wait_ld() {
#if HAS_TCGEN05
    asm volatile("tcgen05.wait::ld.sync.aligned;" ::: "memory");
#endif
}
__device__ __forceinline__ void mbar_init(uint32_t mb, uint32_t n) {
    asm volatile("mbarrier.init.shared.b64 [%0], %1;" :: "r"(mb), "r"(n) : "memory");
}
__device__ __forceinline__ void mbar_expect_tx(uint32_t mb, uint32_t bytes) {
    asm volatile("mbarrier.arrive.expect_tx.shared.b64 _, [%0], %1;"
                 :: "r"(mb), "r"(bytes) : "memory");
}
__device__ __forceinline__ void mbar_arrive(uint32_t mb) {
    asm volatile("mbarrier.arrive.shared.b64 _, [%0];" :: "r"(mb) : "memory");
}
__device__ __forceinline__ void fence_async() {
    asm volatile("fence.proxy.async.shared::cta;" ::: "memory");
}
__device__ __forceinline__ void bulk_copy_g2s(uint32_t dst, const void* src,
                                              uint32_t bytes, uint32_t mb) {
#if HAS_TCGEN05
    asm volatile("cp.async.bulk.shared::cluster.global.mbarrier::complete_tx::bytes "
                 "[%0], [%1], %2, [%3];"
                 :: "r"(dst), "l"(src), "r"(bytes), "r"(mb) : "memory");
#endif
}
__device__ __forceinline__ void mbar_wait(uint32_t mb, uint32_t parity) {
    uint32_t done;
    asm volatile(
        "{\n\t.reg .pred p;\n\t"
        "mbarrier.try_wait.parity.acquire.cta.shared::cta.b64 p, [%1], %2;\n\t"
        "selp.b32 %0, 1, 0, p;\n\t}"
        : "=r"(done) : "r"(mb), "r"(parity) : "memory");
    if (!done) {
        asm volatile(
            "{\n\t.reg .pred P1;\n\t"
            "WL_%=:\n\t"
            "mbarrier.try_wait.parity.acquire.cta.shared::cta.b64 P1, [%0], %1, 0x989680;\n\t"
            "@P1 bra.uni WD_%=;\n\t"
            "bra.uni WL_%=;\n\t"
            "WD_%=:\n\t}"
            :: "r"(mb), "r"(parity) : "memory");
    }
}
__device__ __forceinline__ void ldtm_x32(uint32_t* r, uint32_t addr) {
#if HAS_TCGEN05
    asm volatile("tcgen05.ld.sync.aligned.32x32b.x32.b32 "
                 "{%0,%1,%2,%3,%4,%5,%6,%7,%8,%9,%10,%11,%12,%13,%14,%15,"
                 "%16,%17,%18,%19,%20,%21,%22,%23,%24,%25,%26,%27,%28,%29,%30,%31}, [%32];"
                 : "=r"(r[0]), "=r"(r[1]), "=r"(r[2]), "=r"(r[3]),
                   "=r"(r[4]), "=r"(r[5]), "=r"(r[6]), "=r"(r[7]),
                   "=r"(r[8]), "=r"(r[9]), "=r"(r[10]), "=r"(r[11]),
                   "=r"(r[12]), "=r"(r[13]), "=r"(r[14]), "=r"(r[15]),
                   "=r"(r[16]), "=r"(r[17]), "=r"(r[18]), "=r"(r[19]),
                   "=r"(r[20]), "=r"(r[21]), "=r"(r[22]), "=r"(r[23]),
                   "=r"(r[24]), "=r"(r[25]), "=r"(r[26]), "=r"(r[27]),
                   "=r"(r[28]), "=r"(r[29]), "=r"(r[30]), "=r"(r[31])
                 : "r"(addr));
#else
    for (int i = 0; i < 32; i++) r[i] = 0;
#endif
}

__device__ __forceinline__ uint32_t pack_hl(float x) {
    __nv_bfloat16 h = __float2bfloat16(x);
    float hf = __bfloat162float(h);
    __nv_bfloat16 l = __float2bfloat16(x - hf);
    return (uint32_t)__bfloat16_as_ushort(h) |
           ((uint32_t)__bfloat16_as_ushort(l) << 16);
}
__device__ __forceinline__ uint16_t bf_hi(float x) {
    return __bfloat16_as_ushort(__float2bfloat16(x));
}
__device__ __forceinline__ uint16_t bf_lo(float x) {
    float hf = __bfloat162float(__float2bfloat16(x));
    return __bfloat16_as_ushort(__float2bfloat16(x - hf));
}

// ---------------- weight packing ----------------------------------------------
__global__ void pack_weights_kernel(const float* __restrict__ W1,
                                    const float* __restrict__ W2,
                                    const float* __restrict__ W3,
                                    uint32_t* __restrict__ out) {
    int idx = blockIdx.x * blockDim.x + threadIdx.x;
    if (idx >= 3 * HDIM * HDIM) return;
    const float* W = (idx < HDIM * HDIM) ? W1
                     : (idx < 2 * HDIM * HDIM) ? W2 : W3;
    out[idx] = pack_hl(W[idx % (HDIM * HDIM)]);
}

// ---------------- layer 0: swizzled hi/lo planes + zero head -------------------
__global__ void layer0_kernel(const float* __restrict__ in,
                              const float* __restrict__ W0,
                              const float* __restrict__ b0,
                              const float* __restrict__ in_mean,
                              const float* __restrict__ in_std,
                              uint8_t* __restrict__ H,
                              float* __restrict__ head, int n)
{
    int gid = blockIdx.x * blockDim.x + threadIdx.x;
    if (gid < 3 * n) head[gid] = 0.0f;
    if (gid >= n * 128) return;
    int p = gid >> 7;
    int q = gid & 127;
    int o = q << 1;

    float s  = in[p * 2 + 0];
    float tt = in[p * 2 + 1];
    float sn = (s  - in_mean[0]) / (in_std[0] + 1e-8f);
    float tn = (tt - in_mean[1]) / (in_std[1] + 1e-8f);

    float v[3][2];
    #pragma unroll
    for (int e = 0; e < 2; e++) {
        float w0 = W0[(o + e) * 2 + 0];
        float w1 = W0[(o + e) * 2 + 1];
        float z  = fmaf(w0, sn, fmaf(w1, tn, b0[o + e]));
        float a   = tanhf(z);
        float g   = 1.0f - a * a;
        float hp  = g * w1;
        float hpp = -2.0f * a * w1 * hp;
        v[0][e] = a; v[1][e] = hp; v[2][e] = hpp;
    }

    int pt = p >> 7;
    int r  = p & 127;
    int c  = q >> 5;
    int kk = (q & 31) << 1;
    uint32_t sw = SWZ128((uint32_t)(r * 128 + kk * 2));

    #pragma unroll
    for (int st = 0; st < 3; st++) {
        uint32_t hi = (uint32_t)bf_hi(v[st][0]) | ((uint32_t)bf_hi(v[st][1]) << 16);
        uint32_t lo = (uint32_t)bf_lo(v[st][0]) | ((uint32_t)bf_lo(v[st][1]) << 16);
        *(uint32_t*)(H + blk_off(pt, c, st, 0) + sw) = hi;
        *(uint32_t*)(H + blk_off(pt, c, st, 1) + sw) = lo;
    }
}

// ---------------- persistent tcgen05 hidden layer ------------------------------
// smem map (bytes):
//   [0]    tmem ptr
//   [8..)  mbarriers: full[3]@8..24, done[3]@32..48, mma_done@56, epi_done@64
//   [1024) bias 128 f32 ; [1536) W4 128 f32 ; [2048) sB 8x16KB ; [133120) ring 3x32KB
#define MB_FULL(i) (8u  + (uint32_t)(i) * 8u)
#define MB_DONE(i) (32u + (uint32_t)(i) * 8u)
#define MB_MMA     56u
#define MB_EPID    64u
#define OFF_BIAS 1024
#define OFF_W4   1536
#define OFF_B    2048
#define OFF_A    (2048 + 8 * 16384)
#define SMEM_BYTES (OFF_A + 3 * 32768)   // 231424

__global__ void __launch_bounds__(320, 1)
mma_layer_kernel(const uint8_t* __restrict__ Ain,
                 const uint32_t* __restrict__ Wpk,
                 const float* __restrict__ bias,
                 const float* __restrict__ W4,
                 uint8_t* __restrict__ Aout,
                 float* __restrict__ head,
                 int last)
{
#if HAS_TCGEN05
    extern __shared__ char smem[];
    const uint32_t sbase = smem_u32(smem);
    const int tid  = threadIdx.x;
    const int wid  = tid >> 5;
    const int lane = tid & 31;
    const int ch   = (blockIdx.x >= 74) ? 1 : 0;   // column half (fixed per CTA)
    const int pt0  = blockIdx.x % 74;
    const int ntiles = (pt0 + 74 * 6 < NTILES_PT) ? 7 : 6;

    if (wid == 0) { tc_alloc(sbase, 512); tc_relinq(); }
    if (tid == 0) {
        #pragma unroll
        for (int i = 0; i < 3; i++) { mbar_init(sbase + MB_FULL(i), 1);
                                      mbar_init(sbase + MB_DONE(i), 1); }
        mbar_init(sbase + MB_MMA, 1);
        mbar_init(sbase + MB_EPID, 8);
    }
    if (tid < 128) {
        *(float*)(smem + OFF_BIAS + tid * 4) = bias[ch * 128 + tid];
        if (last) *(float*)(smem + OFF_W4 + tid * 4) = W4[ch * 128 + tid];
    }
    __syncthreads();                    // mbarriers + tmem ptr visible
    const uint32_t tmem = *(const uint32_t*)smem;

    // ---- producer warp (9): stream all A groups through the ring -------------
    if (wid == 9) {
        if (lane == 0) {
            int gg = 0;
            for (int ti = 0; ti < ntiles; ti++) {
                const uint8_t* src = Ain + (size_t)(pt0 + 74 * ti) * TILE_BYTES;
                #pragma unroll 1
                for (int g = 0; g < 12; g++, gg++) {
                    int slot = gg % 3, k = gg / 3;
                    if (gg >= 3) mbar_wait(sbase + MB_DONE(slot), (k - 1) & 1);
                    mbar_expect_tx(sbase + MB_FULL(slot), 32768);
                    bulk_copy_g2s(sbase + OFF_A + slot * 32768,
                                  src + (size_t)g * 32768, 32768,
                                  sbase + MB_FULL(slot));
                }
            }
        }
    }
    // ---- W staging (warps 0-7, 256 threads) ----------------------------------
    else if (wid < 8) {
        #pragma unroll 4
        for (int idx = tid; idx < 8192; idx += 256) {
            int nrow = idx >> 6;
            int q    = idx & 63;
            int k0   = q << 2;
            int c    = k0 >> 6;
            int kk   = k0 & 63;
            uint4 v = *(const uint4*)(Wpk + (size_t)(ch * 128 + nrow) * HDIM + k0);
            uint32_t h0 = __byte_perm(v.x, v.y, 0x5410);
            uint32_t h1 = __byte_perm(v.z, v.w, 0x5410);
            uint32_t l0 = __byte_perm(v.x, v.y, 0x7632);
            uint32_t l1 = __byte_perm(v.z, v.w, 0x7632);
            uint32_t sw = SWZ128(nrow * 128 + kk * 2);
            *(uint2*)(smem + OFF_B + c * 16384 + sw)       = make_uint2(h0, h1);
            *(uint2*)(smem + OFF_B + (4 + c) * 16384 + sw) = make_uint2(l0, l1);
        }
    }
    // warps 0-8 rendezvous: W staged before MMAs read it
    if (wid < 9) asm volatile("bar.sync 1, 288;" ::: "memory");

    // ---- MMA issuer warp (8) --------------------------------------------------
    if (wid == 8 && lane == 0) {
        fence_async();
        int gg = 0;
        #pragma unroll 1
        for (int ti = 0; ti < ntiles; ti++) {
            if (ti > 0) mbar_wait(sbase + MB_EPID, (ti - 1) & 1);
            #pragma unroll 1
            for (int g = 0; g < 12; g++, gg++) {
                int slot = gg % 3, k = gg / 3;
                mbar_wait(sbase + MB_FULL(slot), k & 1);
                int c = g / 3, s = g % 3;
                uint32_t dts = tmem + s * 128;
                #pragma unroll
                for (int prod = 0; prod < 3; prod++) {
                    int ha = (prod == 2) ? 1 : 0;
                    int hb = (prod == 1) ? 1 : 0;
                    uint64_t ad = mk_desc(sbase + OFF_A + slot * 32768 + ha * 16384);
                    uint64_t bd = mk_desc(sbase + OFF_B + (hb * 4 + c) * 16384);
                    #pragma unroll
                    for (int ks = 0; ks < 4; ks++) {
                        uint32_t en = !(c == 0 && prod == 0 && ks == 0);
                        mma_f16_ss(dts, ad + ks * 2, bd + ks * 2, en);
                    }
                }
                tc_commit(sbase + MB_DONE(slot));
            }
            tc_commit(sbase + MB_MMA);
        }
    }

    // ---- epilogue warps (0-7) ---------------------------------------------------
    if (wid < 8) {
        const int sub  = wid & 3;
        const int half = wid >> 2;
        const int c_out = ch * 2 + half;
        #pragma unroll 1
        for (int ti = 0; ti < ntiles; ti++) {
            const int pt = pt0 + 74 * ti;
            const size_t rowBase = (size_t)pt * 128;
            const size_t r = sub * 32 + lane;

            mbar_wait(sbase + MB_MMA, ti & 1);
            tc_fence_after();

            float acc0 = 0.f, acc1 = 0.f, acc2 = 0.f;
            #pragma unroll
            for (int hb = 0; hb < 2; hb++) {
                int colc = half * 64 + hb * 32;   // col offset within this CTA's 128
                uint32_t rz[32], rp[32], rq[32];
                ldtm_x32(rz, tmem + 0   + colc);
                ldtm_x32(rp, tmem + 128 + colc);
                ldtm_x32(rq, tmem + 256 + colc);
                tc_wait_ld();

                float va[32], vp[32], vq[32];
                #pragma unroll
                for (int j = 0; j < 32; j++) {
                    float bv  = *(const float*)(smem + OFF_BIAS + (colc + j) * 4);
                    float z   = __uint_as_float(rz[j]) + bv;
                    float zp  = __uint_as_float(rp[j]);
                    float zpp = __uint_as_float(rq[j]);
                    float a   = tanhf(z);
                    float g   = 1.0f - a * a;
                    float hp  = g * zp;
                    float hpp = fmaf(g, zpp, -2.0f * a * zp * hp);
                    va[j] = a; vp[j] = hp; vq[j] = hpp;
                }

                if (last) {
                    #pragma unroll
                    for (int j = 0; j < 32; j++) {
                        float w4 = *(const float*)(smem + OFF_W4 + (colc + j) * 4);
                        acc0 = fmaf(w4, va[j], acc0);
                        acc1 = fmaf(w4, vp[j], acc1);
                        acc2 = fmaf(w4, vq[j], acc2);
                    }
                } else {
                    // pack pairs and store 4 uint4 per stream (kk = hb*32 .. +31)
                    #pragma unroll
                    for (int qv = 0; qv < 4; qv++) {
                        int j0 = qv * 8;
                        int kk = hb * 32 + j0;
                        uint32_t sw = SWZ128((uint32_t)(r * 128 + kk * 2));
                        uint4 hi0, lo0, hi1, lo1, hi2, lo2;
                        hi0 = make_uint4(
                            (uint32_t)bf_hi(va[j0+0]) | ((uint32_t)bf_hi(va[j0+1]) << 16),
                            (uint32_t)bf_hi(va[j0+2]) | ((uint32_t)bf_hi(va[j0+3]) << 16),
                            (uint32_t)bf_hi(va[j0+4]) | ((uint32_t)bf_hi(va[j0+5]) << 16),
                            (uint32_t)bf_hi(va[j0+6]) | ((uint32_t)bf_hi(va[j0+7]) << 16));
                        lo0 = make_uint4(
                            (uint32_t)bf_lo(va[j0+0]) | ((uint32_t)bf_lo(va[j0+1]) << 16),
                            (uint32_t)bf_lo(va[j0+2]) | ((uint32_t)bf_lo(va[j0+3]) << 16),
                            (uint32_t)bf_lo(va[j0+4]) | ((uint32_t)bf_lo(va[j0+5]) << 16),
                            (uint32_t)bf_lo(va[j0+6]) | ((uint32_t)bf_lo(va[j0+7]) << 16));
                        hi1 = make_uint4(
                            (uint32_t)bf_hi(vp[j0+0]) | ((uint32_t)bf_hi(vp[j0+1]) << 16),
                            (uint32_t)bf_hi(vp[j0+2]) | ((uint32_t)bf_hi(vp[j0+3]) << 16),
                            (uint32_t)bf_hi(vp[j0+4]) | ((uint32_t)bf_hi(vp[j0+5]) << 16),
                            (uint32_t)bf_hi(vp[j0+6]) | ((uint32_t)bf_hi(vp[j0+7]) << 16));
                        lo1 = make_uint4(
                            (uint32_t)bf_lo(vp[j0+0]) | ((uint32_t)bf_lo(vp[j0+1]) << 16),
                            (uint32_t)bf_lo(vp[j0+2]) | ((uint32_t)bf_lo(vp[j0+3]) << 16),
                            (uint32_t)bf_lo(vp[j0+4]) | ((uint32_t)bf_lo(vp[j0+5]) << 16),
                            (uint32_t)bf_lo(vp[j0+6]) | ((uint32_t)bf_lo(vp[j0+7]) << 16));
                        hi2 = make_uint4(
                            (uint32_t)bf_hi(vq[j0+0]) | ((uint32_t)bf_hi(vq[j0+1]) << 16),
                            (uint32_t)bf_hi(vq[j0+2]) | ((uint32_t)bf_hi(vq[j0+3]) << 16),
                            (uint32_t)bf_hi(vq[j0+4]) | ((uint32_t)bf_hi(vq[j0+5]) << 16),
                            (uint32_t)bf_hi(vq[j0+6]) | ((uint32_t)bf_hi(vq[j0+7]) << 16));
                        lo2 = make_uint4(
                            (uint32_t)bf_lo(vq[j0+0]) | ((uint32_t)bf_lo(vq[j0+1]) << 16),
                            (uint32_t)bf_lo(vq[j0+2]) | ((uint32_t)bf_lo(vq[j0+3]) << 16),
                            (uint32_t)bf_lo(vq[j0+4]) | ((uint32_t)bf_lo(vq[j0+5]) << 16),
                            (uint32_t)bf_lo(vq[j0+6]) | ((uint32_t)bf_lo(vq[j0+7]) << 16));
                        *(uint4*)(Aout + blk_off(pt, c_out, 0, 0) + sw) = hi0;
                        *(uint4*)(Aout + blk_off(pt, c_out, 0, 1) + sw) = lo0;
                        *(uint4*)(Aout + blk_off(pt, c_out, 1, 0) + sw) = hi1;
                        *(uint4*)(Aout + blk_off(pt, c_out, 1, 1) + sw) = lo1;
                        *(uint4*)(Aout + blk_off(pt, c_out, 2, 0) + sw) = hi2;
                        *(uint4*)(Aout + blk_off(pt, c_out, 2, 1) + sw) = lo2;
                    }
                }
            }
            if (last) {
                size_t p = rowBase + r;
                atomicAdd(head + p,            acc0);
                atomicAdd(head + NPTS + p,     acc1);
                atomicAdd(head + 2 * NPTS + p, acc2);
            }
            // TMEM reads of this tile done -> release D for next tile
            if (lane == 0) mbar_arrive(sbase + MB_EPID);
        }
    }

    __syncthreads();
    if (wid == 0) tc_dealloc(tmem, 512);
#endif  // HAS_TCGEN05
}

// ---------------- final: logistic terms from head sums -------------------------
__global__ void final2_kernel(const float* __restrict__ head,
                              const float* __restrict__ b4,
                              const float* __restrict__ lgr,
                              const float* __restrict__ lcc,
                              const float* __restrict__ lil,
                              const float* __restrict__ tgt_mean,
                              const float* __restrict__ tgt_std,
                              float* __restrict__ out, int n)
{
    int i = blockIdx.x * blockDim.x + threadIdx.x;
    if (i >= n) return;

    float ts = tgt_std[0];
    float tm = tgt_mean[0];
    float r_ = expf(-lgr[0]);
    float Kc = 0.2f + 0.8f / (1.0f + expf(-lcc[0]));
    float Cc = 0.1f / (1.0f + expf(-lil[0]));

    float U   = (head[i] + b4[0]) * ts + tm;
    float Ut  = head[n + i] * ts;
    float Utt = head[2 * n + i] * ts;

    float d  = (U - Cc) / (Kc - Cc);
    float G  = r_ * (U - Cc) * (1.0f - d);
    float F  = Ut - G;
    float Gt = r_ * Ut * (1.0f - 2.0f * d);
    float Ft = Utt - Gt;

    out[i]         = U;
    out[n + i]     = F;
    out[2 * n + i] = Ft;
}

// ---------------------------------------------------------------------------
extern "C" void kernel_launch(void* const* d_in, const int* in_sizes, int n_in,
                              void* d_out, int out_size)
{
    const float* inputs  = (const float*)d_in[0];
    const float* W0      = (const float*)d_in[1];
    const float* b0      = (const float*)d_in[2];
    const float* W1      = (const float*)d_in[3];
    const float* b1      = (const float*)d_in[4];
    const float* W2      = (const float*)d_in[5];
    const float* b2      = (const float*)d_in[6];
    const float* W3      = (const float*)d_in[7];
    const float* b3      = (const float*)d_in[8];
    const float* W4      = (const float*)d_in[9];
    const float* b4      = (const float*)d_in[10];
    const float* lgr     = (const float*)d_in[11];
    const float* lcc     = (const float*)d_in[12];
    const float* lil     = (const float*)d_in[13];
    const float* in_mean = (const float*)d_in[14];
    const float* in_std  = (const float*)d_in[15];
    const float* tgt_mean= (const float*)d_in[16];
    const float* tgt_std = (const float*)d_in[17];

    int n = in_sizes[0] / 2;
    if (n > NPTS) n = NPTS;

    uint8_t *actA, *actB;
    uint32_t *wpk;
    float *head;
    cudaGetSymbolAddress((void**)&actA, g_actA);
    cudaGetSymbolAddress((void**)&actB, g_actB);
    cudaGetSymbolAddress((void**)&wpk, g_Wpk);
    cudaGetSymbolAddress((void**)&head, g_head);

    cudaFuncSetAttribute(mma_layer_kernel,
                         cudaFuncAttributeMaxDynamicSharedMemorySize, SMEM_BYTES);

    pack_weights_kernel<<<(3 * HDIM * HDIM + 255) / 256, 256>>>(W1, W2, W3, wpk);
    layer0_kernel<<<(n * 128 + 255) / 256, 256>>>(inputs, W0, b0, in_mean, in_std,
                                                  actA, head, n);

    mma_layer_kernel<<<148, 320, SMEM_BYTES>>>(actA, wpk,                   b1, W4, actB, head, 0);
    mma_layer_kernel<<<148, 320, SMEM_BYTES>>>(actB, wpk + HDIM * HDIM,     b2, W4, actA, head, 0);
    mma_layer_kernel<<<148, 320, SMEM_BYTES>>>(actA, wpk + 2 * HDIM * HDIM, b3, W4, actB, head, 1);

    final2_kernel<<<(n + 255) / 256, 256>>>(head, b4, lgr, lcc, lil,
                                            tgt_mean, tgt_std, (float*)d_out, n);
}